// round 11
// baseline (speedup 1.0000x reference)
#include <cuda_runtime.h>
#include <cstdint>

// HONU order-2 as triangular register-blocked GEMM (R10 structure, R11 diet):
//   U[j][n] = W[p(j,n)] (n>=j) else 0;  Y = X U;  out = rowsum(Y .* X) + b
// Warp C owns column blocks A = {4C..4C+3}, B = {60-4C..63-4C}.
// Loop fully specialized on C (8-way switch): compile-time trips, immediate
// offsets, merged A/B loops sharing the x load. U pre-expanded to global by
// a pre-kernel, read warp-uniform via ld.global.nc (L1tex port); x via smem
// crossbar -> operand traffic split across two ports.

#define THREADS 256
#define XT 33                    // xs_T row stride (floats)

__device__ __align__(16) float A_g[64 * 64];

__global__ void expand_kernel(const float* __restrict__ W) {
    int i = blockIdx.x * 256 + threadIdx.x;            // 4096 elements
    if (i < 64 * 64) {
        int j = i >> 6, n = i & 63;
        float v = 0.0f;
        if (n >= j) v = W[j * 64 - ((j * (j - 1)) >> 1) + (n - j)];
        A_g[i] = v;
    }
}

__device__ __forceinline__ void fma2(uint64_t& d, uint64_t a, uint64_t b) {
    asm("fma.rn.f32x2 %0, %1, %2, %0;" : "+l"(d) : "l"(a), "l"(b));
}
__device__ __forceinline__ float lds32(unsigned addr) {
    float v;
    asm volatile("ld.shared.f32 %0, [%1];" : "=f"(v) : "r"(addr));
    return v;
}
__device__ __forceinline__ uint64_t splat(float x) {
    uint64_t d;
    asm("mov.b64 %0, {%1,%1};" : "=l"(d) : "r"(__float_as_uint(x)));
    return d;
}
__device__ __forceinline__ void ldg_v2u64(uint64_t& a, uint64_t& b, const void* p) {
    asm("ld.global.nc.v2.b64 {%0,%1}, [%2];" : "=l"(a), "=l"(b) : "l"(p));
}
__device__ __forceinline__ float lo32(uint64_t v) {
    uint32_t r;
    asm("mov.b64 {%0,_}, %1;" : "=r"(r) : "l"(v));
    return __uint_as_float(r);
}
__device__ __forceinline__ float hi32(uint64_t v) {
    uint32_t r;
    asm("mov.b64 {_,%0}, %1;" : "=r"(r) : "l"(v));
    return __uint_as_float(r);
}

template <int C>
__device__ __forceinline__ float body(unsigned xtb) {
    constexpr int colA  = 4 * C;
    constexpr int colB  = 60 - 4 * C;
    constexpr int tripA = 4 * C + 4;
    constexpr int kmax  = 64 - 4 * C;     // >= tripA for C in 0..7
    const char* Ab = reinterpret_cast<const char*>(A_g);

    uint64_t a0 = 0, a1 = 0, b0 = 0, b1 = 0;
    #pragma unroll
    for (int k = 0; k < kmax; ++k) {
        uint64_t xk2 = splat(lds32(xtb + k * (XT * 4)));
        if (k < tripA) {                  // compile-time pruned by unroll
            uint64_t u0, u1;
            ldg_v2u64(u0, u1, Ab + (k * 64 + colA) * 4);
            fma2(a0, u0, xk2);
            fma2(a1, u1, xk2);
        }
        uint64_t v0, v1;
        ldg_v2u64(v0, v1, Ab + (k * 64 + colB) * 4);
        fma2(b0, v0, xk2);
        fma2(b1, v1, xk2);
    }

    float p = 0.0f;
    p = fmaf(lo32(a0), lds32(xtb + (colA + 0) * (XT * 4)), p);
    p = fmaf(hi32(a0), lds32(xtb + (colA + 1) * (XT * 4)), p);
    p = fmaf(lo32(a1), lds32(xtb + (colA + 2) * (XT * 4)), p);
    p = fmaf(hi32(a1), lds32(xtb + (colA + 3) * (XT * 4)), p);
    p = fmaf(lo32(b0), lds32(xtb + (colB + 0) * (XT * 4)), p);
    p = fmaf(hi32(b0), lds32(xtb + (colB + 1) * (XT * 4)), p);
    p = fmaf(lo32(b1), lds32(xtb + (colB + 2) * (XT * 4)), p);
    p = fmaf(hi32(b1), lds32(xtb + (colB + 3) * (XT * 4)), p);
    return p;
}

__global__ void __launch_bounds__(THREADS) honu_kernel(
    const float* __restrict__ x, const float* __restrict__ bias,
    float* __restrict__ out)
{
    __shared__ float xs_T[64 * XT];                  // 8.25 KB transposed tile
    __shared__ float part[8][32];

    const int tid  = threadIdx.x;
    const int wid  = tid >> 5;                       // column-pair C (uniform)
    const int lane = tid & 31;                       // row within tile
    const int row0 = blockIdx.x * 32;

    // --- Stage x tile transposed: xs_T[k][r] = x[row0+r][k]
    {
        const float4* xg4 = reinterpret_cast<const float4*>(x + (size_t)row0 * 64);
        #pragma unroll
        for (int it = 0; it < 2; ++it) {
            int i = it * THREADS + tid;              // 0..511 float4s
            int r = i >> 4, c4 = i & 15;
            float4 v = xg4[i];
            xs_T[(4 * c4 + 0) * XT + r] = v.x;
            xs_T[(4 * c4 + 1) * XT + r] = v.y;
            xs_T[(4 * c4 + 2) * XT + r] = v.z;
            xs_T[(4 * c4 + 3) * XT + r] = v.w;
        }
    }
    __syncthreads();

    const unsigned xtb = (unsigned)__cvta_generic_to_shared(xs_T) + lane * 4;

    float p;
    switch (wid) {
        case 0: p = body<0>(xtb); break;
        case 1: p = body<1>(xtb); break;
        case 2: p = body<2>(xtb); break;
        case 3: p = body<3>(xtb); break;
        case 4: p = body<4>(xtb); break;
        case 5: p = body<5>(xtb); break;
        case 6: p = body<6>(xtb); break;
        default: p = body<7>(xtb); break;
    }

    part[wid][lane] = p;
    __syncthreads();

    // --- Warp 0 combines the 8 column-pair partials per row
    if (wid == 0) {
        float s = part[0][lane];
        #pragma unroll
        for (int w = 1; w < 8; ++w) s += part[w][lane];
        out[row0 + lane] = s + __ldg(bias);
    }
}

extern "C" void kernel_launch(void* const* d_in, const int* in_sizes, int n_in,
                              void* d_out, int out_size) {
    const float* x = (const float*)d_in[0];   // (16384, 64) f32
    const float* W = (const float*)d_in[1];   // (2145,)  f32 (first 2080 used)
    const float* b = (const float*)d_in[2];   // (1,)     f32
    float*     out = (float*)d_out;           // (16384,) f32

    expand_kernel<<<16, 256>>>(W);

    const int blocks = out_size / 32;         // 512 CTAs x 256 threads
    honu_kernel<<<blocks, THREADS>>>(x, b, out);
}

// round 12
// speedup vs baseline: 1.2157x; 1.2157x over previous
#include <cuda_runtime.h>
#include <cstdint>

// HONU order-2 as triangular register-blocked GEMM.
//   U[j][n] = W[p(j,n)] (n>=j) else 0;  Y = X U;  out = rowsum(Y .* X) + b
// R12 = R10 structure (U operand in SMEM, uniform LDS.v2.b64 -> proven 44%
// issue) + R11 diet (8-way warp-id specialization: compile-time trips,
// immediate offsets; merged A/B loop sharing the x load) + linear U copy
// from a pre-expanded global (replaces per-CTA arithmetic expand).

#define THREADS 256
#define XT 33                    // xs_T row stride (floats)

__device__ __align__(16) float A_g[64 * 64];

__global__ void expand_kernel(const float* __restrict__ W) {
    int i = blockIdx.x * 256 + threadIdx.x;            // 4096 elements
    if (i < 64 * 64) {
        int j = i >> 6, n = i & 63;
        float v = 0.0f;
        if (n >= j) v = W[j * 64 - ((j * (j - 1)) >> 1) + (n - j)];
        A_g[i] = v;
    }
}

__device__ __forceinline__ void fma2(uint64_t& d, uint64_t a, uint64_t b) {
    asm("fma.rn.f32x2 %0, %1, %2, %0;" : "+l"(d) : "l"(a), "l"(b));
}
__device__ __forceinline__ void lds_v2u64(uint64_t& a, uint64_t& b, unsigned addr) {
    asm volatile("ld.shared.v2.b64 {%0,%1}, [%2];" : "=l"(a), "=l"(b) : "r"(addr));
}
__device__ __forceinline__ float lds32(unsigned addr) {
    float v;
    asm volatile("ld.shared.f32 %0, [%1];" : "=f"(v) : "r"(addr));
    return v;
}
__device__ __forceinline__ uint64_t splat(float x) {
    uint64_t d;
    asm("mov.b64 %0, {%1,%1};" : "=l"(d) : "r"(__float_as_uint(x)));
    return d;
}
__device__ __forceinline__ float lo32(uint64_t v) {
    uint32_t r; asm("mov.b64 {%0,_}, %1;" : "=r"(r) : "l"(v));
    return __uint_as_float(r);
}
__device__ __forceinline__ float hi32(uint64_t v) {
    uint32_t r; asm("mov.b64 {_,%0}, %1;" : "=r"(r) : "l"(v));
    return __uint_as_float(r);
}

template <int C>
__device__ __forceinline__ float body(unsigned xtb, unsigned ub) {
    constexpr int colA  = 4 * C;
    constexpr int colB  = 60 - 4 * C;
    constexpr int tripA = 4 * C + 4;      // A block: k <= colA+3
    constexpr int kmax  = 64 - 4 * C;     // B block: k <= colB+3 (>= tripA)

    uint64_t a0 = 0, a1 = 0, b0 = 0, b1 = 0;
    #pragma unroll
    for (int k = 0; k < kmax; ++k) {
        uint64_t xk2 = splat(lds32(xtb + k * (XT * 4)));     // 32 rows: 1 wf
        if (k < tripA) {                   // compile-time pruned
            uint64_t u0, u1;
            lds_v2u64(u0, u1, ub + (k * 64 + colA) * 4);     // uniform: 1 wf
            fma2(a0, u0, xk2);
            fma2(a1, u1, xk2);
        }
        uint64_t v0, v1;
        lds_v2u64(v0, v1, ub + (k * 64 + colB) * 4);
        fma2(b0, v0, xk2);
        fma2(b1, v1, xk2);
    }

    float p = 0.0f;
    p = fmaf(lo32(a0), lds32(xtb + (colA + 0) * (XT * 4)), p);
    p = fmaf(hi32(a0), lds32(xtb + (colA + 1) * (XT * 4)), p);
    p = fmaf(lo32(a1), lds32(xtb + (colA + 2) * (XT * 4)), p);
    p = fmaf(hi32(a1), lds32(xtb + (colA + 3) * (XT * 4)), p);
    p = fmaf(lo32(b0), lds32(xtb + (colB + 0) * (XT * 4)), p);
    p = fmaf(hi32(b0), lds32(xtb + (colB + 1) * (XT * 4)), p);
    p = fmaf(lo32(b1), lds32(xtb + (colB + 2) * (XT * 4)), p);
    p = fmaf(hi32(b1), lds32(xtb + (colB + 3) * (XT * 4)), p);
    return p;
}

__global__ void __launch_bounds__(THREADS) honu_kernel(
    const float* __restrict__ x, const float* __restrict__ bias,
    float* __restrict__ out)
{
    __shared__ __align__(16) float U_s[64 * 64];     // 16 KB
    __shared__ float xs_T[64 * XT];                  // 8.25 KB transposed tile
    __shared__ float part[8][32];

    const int tid  = threadIdx.x;
    const int wid  = tid >> 5;                       // column-pair C (uniform)
    const int lane = tid & 31;
    const int row0 = blockIdx.x * 32;

    // --- Copy pre-expanded U (1024 float4s: 4 LDG.128 + 4 STS.128 / thread)
    {
        const float4* Ag4 = reinterpret_cast<const float4*>(A_g);
        float4*       Us4 = reinterpret_cast<float4*>(U_s);
        #pragma unroll
        for (int it = 0; it < 4; ++it)
            Us4[it * THREADS + tid] = Ag4[it * THREADS + tid];
    }
    // --- Stage x tile transposed: xs_T[k][r] = x[row0+r][k]
    {
        const float4* xg4 = reinterpret_cast<const float4*>(x + (size_t)row0 * 64);
        #pragma unroll
        for (int it = 0; it < 2; ++it) {
            int i = it * THREADS + tid;              // 0..511 float4s
            int r = i >> 4, c4 = i & 15;
            float4 v = xg4[i];
            xs_T[(4 * c4 + 0) * XT + r] = v.x;
            xs_T[(4 * c4 + 1) * XT + r] = v.y;
            xs_T[(4 * c4 + 2) * XT + r] = v.z;
            xs_T[(4 * c4 + 3) * XT + r] = v.w;
        }
    }
    __syncthreads();

    const unsigned xtb = (unsigned)__cvta_generic_to_shared(xs_T) + lane * 4;
    const unsigned ub  = (unsigned)__cvta_generic_to_shared(U_s);

    float p;
    switch (wid) {
        case 0: p = body<0>(xtb, ub); break;
        case 1: p = body<1>(xtb, ub); break;
        case 2: p = body<2>(xtb, ub); break;
        case 3: p = body<3>(xtb, ub); break;
        case 4: p = body<4>(xtb, ub); break;
        case 5: p = body<5>(xtb, ub); break;
        case 6: p = body<6>(xtb, ub); break;
        default: p = body<7>(xtb, ub); break;
    }

    part[wid][lane] = p;
    __syncthreads();

    if (wid == 0) {
        float s = part[0][lane];
        #pragma unroll
        for (int w = 1; w < 8; ++w) s += part[w][lane];
        out[row0 + lane] = s + __ldg(bias);
    }
}

extern "C" void kernel_launch(void* const* d_in, const int* in_sizes, int n_in,
                              void* d_out, int out_size) {
    const float* x = (const float*)d_in[0];   // (16384, 64) f32
    const float* W = (const float*)d_in[1];   // (2145,)  f32 (first 2080 used)
    const float* b = (const float*)d_in[2];   // (1,)     f32
    float*     out = (float*)d_out;           // (16384,) f32

    expand_kernel<<<16, 256>>>(W);

    const int blocks = out_size / 32;         // 512 CTAs x 256 threads
    honu_kernel<<<blocks, THREADS>>>(x, b, out);
}